// round 3
// baseline (speedup 1.0000x reference)
#include <cuda_runtime.h>

#define BATCH 4
#define NN1 512
#define NN2 512
#define DIM 256

// scratch (allocation-free rule: device globals)
__device__ float g_xp[BATCH * NN1 * DIM];   // x @ Wx + b1
__device__ float g_yp[BATCH * NN2 * DIM];   // y @ Wy

// ---------------------------------------------------------------------------
// Kernel 1: projection GEMM.
//   z==0:  g_xp[m][e] = sum_k x[m][k] * W1[k][e]        + b1[e]
//   z==1:  g_yp[m][e] = sum_k y[m][k] * W1[(256+k)][e]
// M = 2048 rows per input, K = N = 256.
// Tiling: 64x64 output tile, BK=32, 256 threads, 4x4 micro-tile.
// ---------------------------------------------------------------------------
#define PBM 64
#define PBN 64
#define PBK 32

__global__ __launch_bounds__(256)
void proj_kernel(const float* __restrict__ x,
                 const float* __restrict__ y,
                 const float* __restrict__ W1,
                 const float* __restrict__ b1)
{
    __shared__ float As[PBK][68];   // [k][m], padded stride 68 (16B aligned rows)
    __shared__ float Bs[PBK][68];   // [k][e]

    const int which = blockIdx.z;
    const float* A = which ? y : x;
    float* C = which ? g_yp : g_xp;
    const float* W = W1 + (which ? DIM * DIM : 0);

    const int m0 = blockIdx.x * PBM;
    const int e0 = blockIdx.y * PBN;
    const int tid = threadIdx.x;
    const int tx = tid % 16;   // e group (4 wide)
    const int ty = tid / 16;   // m group (4 wide)

    float acc[4][4] = {};

    for (int k0 = 0; k0 < DIM; k0 += PBK) {
        // A tile 64x32 -> As[k][m] (transposed store)
        #pragma unroll
        for (int p = 0; p < 2; p++) {
            int r = tid / 8 + p * 32;        // 0..63
            int c = (tid % 8) * 4;           // 0..28
            float4 v = *reinterpret_cast<const float4*>(&A[(m0 + r) * DIM + k0 + c]);
            As[c + 0][r] = v.x; As[c + 1][r] = v.y;
            As[c + 2][r] = v.z; As[c + 3][r] = v.w;
        }
        // W tile 32x64 -> Bs[k][e]
        #pragma unroll
        for (int p = 0; p < 2; p++) {
            int r = tid / 16 + p * 16;       // 0..31
            int c = (tid % 16) * 4;          // 0..60
            *reinterpret_cast<float4*>(&Bs[r][c]) =
                *reinterpret_cast<const float4*>(&W[(k0 + r) * DIM + e0 + c]);
        }
        __syncthreads();

        #pragma unroll
        for (int kk = 0; kk < PBK; kk++) {
            float4 av4 = *reinterpret_cast<const float4*>(&As[kk][ty * 4]);
            float4 bv4 = *reinterpret_cast<const float4*>(&Bs[kk][tx * 4]);
            float av[4] = {av4.x, av4.y, av4.z, av4.w};
            float bv[4] = {bv4.x, bv4.y, bv4.z, bv4.w};
            #pragma unroll
            for (int i = 0; i < 4; i++)
                #pragma unroll
                for (int j = 0; j < 4; j++)
                    acc[i][j] = fmaf(av[i], bv[j], acc[i][j]);
        }
        __syncthreads();
    }

    #pragma unroll
    for (int i = 0; i < 4; i++) {
        const int m = m0 + ty * 4 + i;
        #pragma unroll
        for (int j = 0; j < 4; j++) {
            const int e = e0 + tx * 4 + j;
            float v = acc[i][j];
            if (!which) v += b1[e];
            C[m * DIM + e] = v;
        }
    }
}

// ---------------------------------------------------------------------------
// Kernel 2: fused cross + gelu + reduction over d.
//   out[b][n][m] = sum_d gelu(g_xp[b,n,d] + g_yp[b,m,d]) * W2[d] + b2
// Tile 32(n) x 32(m), 128 threads, each thread 2x4 outputs. d chunked at 128.
// gelu via tanh-form using hardware MUFU.TANH:
//   g = 0.5*h*(1 + tanh(h*(0.79788456 + 0.035677408*h^2)))
// ---------------------------------------------------------------------------
#define TBN 32
#define TBM 32
#define DK  128

__global__ __launch_bounds__(128)
void cross_kernel(const float* __restrict__ W2,
                  const float* __restrict__ b2,
                  float* __restrict__ out)
{
    __shared__ float sx[TBN][DK + 1];   // stride 129: conflict-free compute reads
    __shared__ float sy[TBM][DK + 1];
    __shared__ float sw[DK];

    const int b  = blockIdx.z;
    const int n0 = blockIdx.x * TBN;
    const int m0 = blockIdx.y * TBM;
    const int tid = threadIdx.x;         // 0..127
    const int tx = tid % 8;              // m group: 4 outputs
    const int ty = tid / 8;              // n group: 2 outputs

    const float* xp = g_xp + (b * NN1 + n0) * DIM;
    const float* yp = g_yp + (b * NN2 + m0) * DIM;

    float acc[2][4] = {};

    for (int d0 = 0; d0 < DIM; d0 += DK) {
        // load 32x128 tiles of xp and yp
        #pragma unroll
        for (int p = 0; p < 8; p++) {
            int r = tid / 32 + p * 4;        // 0..31
            int c = (tid % 32) * 4;          // 0..124
            float4 vx = *reinterpret_cast<const float4*>(&xp[r * DIM + d0 + c]);
            sx[r][c + 0] = vx.x; sx[r][c + 1] = vx.y;
            sx[r][c + 2] = vx.z; sx[r][c + 3] = vx.w;
            float4 vy = *reinterpret_cast<const float4*>(&yp[r * DIM + d0 + c]);
            sy[r][c + 0] = vy.x; sy[r][c + 1] = vy.y;
            sy[r][c + 2] = vy.z; sy[r][c + 3] = vy.w;
        }
        if (tid < DK) sw[tid] = W2[d0 + tid];
        __syncthreads();

        #pragma unroll 4
        for (int d = 0; d < DK; d++) {
            const float w2 = sw[d];
            float a[2], bb[4];
            a[0] = sx[ty * 2 + 0][d];
            a[1] = sx[ty * 2 + 1][d];
            #pragma unroll
            for (int j = 0; j < 4; j++) bb[j] = sy[tx * 4 + j][d];

            #pragma unroll
            for (int i = 0; i < 2; i++) {
                #pragma unroll
                for (int j = 0; j < 4; j++) {
                    float h  = a[i] + bb[j];
                    float x2 = h * h;
                    float pp = fmaf(0.0356774081f, x2, 0.7978845608f);
                    float t  = h * pp;
                    float th;
                    asm("tanh.approx.f32 %0, %1;" : "=f"(th) : "f"(t));
                    float hh = 0.5f * h;
                    float g  = fmaf(hh, th, hh);
                    acc[i][j] = fmaf(g, w2, acc[i][j]);
                }
            }
        }
        __syncthreads();
    }

    const float bias = b2[0];
    #pragma unroll
    for (int i = 0; i < 2; i++) {
        const int n = n0 + ty * 2 + i;
        #pragma unroll
        for (int j = 0; j < 4; j++) {
            const int m = m0 + tx * 4 + j;
            out[(b * NN1 + n) * NN2 + m] = acc[i][j] + bias;
        }
    }
}

// ---------------------------------------------------------------------------
extern "C" void kernel_launch(void* const* d_in, const int* in_sizes, int n_in,
                              void* d_out, int out_size)
{
    const float* x  = (const float*)d_in[0];   // (4, 512, 256)
    const float* y  = (const float*)d_in[1];   // (4, 512, 256)
    const float* W1 = (const float*)d_in[2];   // (512, 256)
    const float* b1 = (const float*)d_in[3];   // (256,)
    const float* W2 = (const float*)d_in[4];   // (256, 1)
    const float* b2 = (const float*)d_in[5];   // (1,)
    float* out = (float*)d_out;                // (4, 512, 512)

    (void)in_sizes; (void)n_in; (void)out_size;

    // projections: M=2048 rows each, grid (2048/64, 256/64, 2)
    dim3 pgrid(BATCH * NN1 / PBM, DIM / PBN, 2);
    proj_kernel<<<pgrid, 256>>>(x, y, W1, b1);

    // fused cross: grid (512/32, 512/32, 4) = 1024 blocks
    dim3 cgrid(NN1 / TBN, NN2 / TBM, BATCH);
    cross_kernel<<<cgrid, 128>>>(W2, b2, out);
}